// round 13
// baseline (speedup 1.0000x reference)
#include <cuda_runtime.h>

#define NANCH 8732
#define NCLS  599
#define MC    300
#define CAPN  1024
#define ROWD  604
#define TH_COLLECT 0.9999f

typedef unsigned int u32;
typedef unsigned long long u64;

// ------------------- static device scratch (no allocations) -------------------
__device__ u64 g_col[2 * CAPN];        // collected candidate sortkeys
__device__ u32 g_ccnt[2];              // per-image collected counters (self-resetting)

// -------- speculative collect: all scores >= TH_COLLECT, 2 anchors/warp -------
__device__ __forceinline__ void col_append(int b, u32 c, float f, u32 a) {
    u32 p = atomicAdd(&g_ccnt[b], 1u);
    if (p < CAPN)
        g_col[b * CAPN + p] =
            ((u64)c << 46) | ((u64)__float_as_uint(f) << 14) | (u64)(0x3FFFu - a);
}

__global__ void __launch_bounds__(256) k_collect(const float* __restrict__ in) {
    int b    = blockIdx.y;
    int w    = threadIdx.x >> 5, lane = threadIdx.x & 31;
    int a0   = blockIdx.x * 16 + w * 2;
    bool ok0 = a0 < NANCH, ok1 = a0 + 1 < NANCH;

    const float4* r0 = (const float4*)(in + ((size_t)b * NANCH + a0) * ROWD);
    const float4* r1 = (const float4*)(in + ((size_t)b * NANCH + a0 + 1) * ROWD);

    float4 v[5], u[5];
    #pragma unroll
    for (int i = 0; i < 5; i++) {
        int idx = lane + 32 * i;                 // 0..150 valid (151 float4/row)
        bool inr = idx < 151;
        v[i] = (ok0 && inr) ? __ldg(&r0[idx]) : make_float4(0.f, 0.f, 0.f, 0.f);
        u[i] = (ok1 && inr) ? __ldg(&r1[idx]) : make_float4(0.f, 0.f, 0.f, 0.f);
    }

    #pragma unroll
    for (int i = 0; i < 5; i++) {
        int base = 4 * (lane + 32 * i);
        float fv[4] = {v[i].x, v[i].y, v[i].z, v[i].w};
        float fu[4] = {u[i].x, u[i].y, u[i].z, u[i].w};
        #pragma unroll
        for (int s = 0; s < 4; s++) {
            int j = base + s;                    // raw column; class = j-1
            if (j >= 1 && j <= NCLS) {
                if (fv[s] >= TH_COLLECT) col_append(b, (u32)(j - 1), fv[s], (u32)a0);
                if (fu[s] >= TH_COLLECT) col_append(b, (u32)(j - 1), fu[s], (u32)(a0 + 1));
            }
        }
    }
}

// ------------- hybrid bitonic 1024 desc (shfl j<=16, smem j>=32) --------------
__device__ __forceinline__ u64 sort1024_desc(u64 p, u64* sm, int tid) {
    #pragma unroll
    for (int k = 2; k <= 32; k <<= 1)
        #pragma unroll
        for (int j = k >> 1; j; j >>= 1) {
            u64 q = __shfl_xor_sync(0xffffffffu, p, j);
            bool keep_max = ((tid & k) == 0) == ((tid & j) == 0);
            bool sw = keep_max ? (q > p) : (q < p);
            if (sw) p = q;
        }
    sm[tid] = p;
    __syncthreads();
    for (int k = 64; k <= 1024; k <<= 1) {
        for (int j = k >> 1; j >= 32; j >>= 1) {
            int x = tid ^ j;
            if (x > tid) {
                u64 a = sm[tid], bb = sm[x];
                bool sw = ((tid & k) == 0) ? (a < bb) : (a > bb);
                if (sw) { sm[tid] = bb; sm[x] = a; }
            }
            __syncthreads();
        }
        p = sm[tid];
        #pragma unroll
        for (int j = 16; j; j >>= 1) {
            u64 q = __shfl_xor_sync(0xffffffffu, p, j);
            bool keep_max = ((tid & k) == 0) == ((tid & j) == 0);
            bool sw = keep_max ? (q > p) : (q < p);
            if (sw) p = q;
        }
        sm[tid] = p;
        __syncthreads();
    }
    return p;
}

// --------------------------- shared final-stage pieces ------------------------
struct Cand { bool valid; u32 c, ub, anch; int r; };

__device__ __forceinline__ Cand extract_rank(const float* __restrict__ in, int b, int tid,
        u32 n, u64* skey, u32* sclass, float4* sbox, float* sarea, u32* skept) {
    Cand cd; cd.valid = (u32)tid < n; cd.c = 0; cd.ub = 0; cd.anch = 0; cd.r = 0;
    skept[tid] = 0;
    if (cd.valid) {
        u64 key = skey[tid];
        cd.c    = (u32)(key >> 46);
        cd.ub   = (u32)(key >> 14);
        cd.anch = 0x3FFFu - (u32)(key & 0x3FFFu);
        sclass[tid] = cd.c;
        const float4 bx = *(const float4*)(in + ((size_t)b * NANCH + cd.anch) * ROWD + 600);
        // bx = (cx, cy, w, h) -> exact reference corner encode
        float y0 = __fsub_rn(bx.y, __fmul_rn(bx.w, 0.5f));
        float x0 = __fsub_rn(bx.x, __fmul_rn(bx.z, 0.5f));
        float y1 = __fadd_rn(bx.y, __fmul_rn(bx.w, 0.5f));
        float x1 = __fadd_rn(bx.x, __fmul_rn(bx.z, 0.5f));
        sbox[tid]  = make_float4(y0, x0, y1, x1);
        sarea[tid] = __fmul_rn(__fsub_rn(y1, y0), __fsub_rn(x1, x0));
        int r = 0;
        while (tid - r - 1 >= 0 && (u32)(skey[tid - r - 1] >> 46) == cd.c) r++;
        cd.r = r;
    }
    __syncthreads();
    return cd;
}

__device__ __forceinline__ bool iou_gt45(float4 bj, float aj, float4 bk, float ak) {
    float ih = fmaxf(__fsub_rn(fminf(bj.z, bk.z), fmaxf(bj.x, bk.x)), 0.f);
    float iw = fmaxf(__fsub_rn(fminf(bj.w, bk.w), fmaxf(bj.y, bk.y)), 0.f);
    float inter = __fmul_rn(ih, iw);
    float uni   = __fsub_rn(__fadd_rn(aj, ak), inter);
    return uni > 0.f && __fdiv_rn(inter, uni) > 0.45f;
}

// parallel suppressor masks + bit-only leader resolve (exact greedy semantics)
__device__ __forceinline__ void nms_mark(int tid, u32 n, const Cand& cd,
        u32* sclass, float4* sbox, float* sarea, u32* skept, u64* ssup) {
    u64 mymask = 0;
    if (cd.valid && cd.r >= 1 && cd.r < 64) {
        int seg0 = tid - cd.r;
        float4 bk = sbox[tid];
        float  ak = sarea[tid];
        for (int jj = 0; jj < cd.r; jj++)
            mymask |= ((u64)iou_gt45(sbox[seg0 + jj], sarea[seg0 + jj], bk, ak)) << jj;
    }
    ssup[tid] = mymask;
    __syncthreads();

    if (cd.valid && cd.r == 0) {                 // one leader per class segment
        skept[tid] = 1;
        u64 km = 1;                              // bit jj = segment member jj kept
        for (int k = tid + 1; k < (int)n && sclass[k] == cd.c; k++) {
            int kk = k - tid;
            bool kept;
            if (kk < 64) {
                kept = (ssup[k] & km) == 0ull;
                if (kept) km |= 1ull << kk;
            } else {                             // exact serial (essentially never)
                kept = true;
                float4 bk = sbox[k];
                float  ak = sarea[k];
                for (int j = tid; j < k; j++)
                    if (skept[j] && iou_gt45(sbox[j], sarea[j], bk, ak)) { kept = false; break; }
            }
            skept[k] = kept ? 1u : 0u;
        }
    }
    __syncthreads();
}

// sort packed final keys (anchor embedded in low 14 bits) and emit top-200
__device__ __forceinline__ void sort_emit(const float* __restrict__ in,
        float* __restrict__ out, int b, int tid, u64 fk, u64* skey) {
    sort1024_desc(fk, skey, tid);
    if (tid < 200) {
        u64 key = skey[tid];
        float cls = 0.f, score = 0.f, ocx = 0.f, ocy = 0.f, otw = 0.f, oth = 0.f;
        if (key) {
            score = __uint_as_float((u32)(key >> 32));
            u32 flat = 0x3FFFFu ^ ((u32)(key >> 14) & 0x3FFFFu);
            cls = (float)(flat / MC + 1);
            u32 anchor = (u32)key & 0x3FFFu;
            const float4 bx = *(const float4*)(in + ((size_t)b * NANCH + anchor) * ROWD + 600);
            float y0 = __fsub_rn(bx.y, __fmul_rn(bx.w, 0.5f));
            float x0 = __fsub_rn(bx.x, __fmul_rn(bx.z, 0.5f));
            float y1 = __fadd_rn(bx.y, __fmul_rn(bx.w, 0.5f));
            float x1 = __fadd_rn(bx.x, __fmul_rn(bx.z, 0.5f));
            otw = __fsub_rn(x1, x0);
            oth = __fsub_rn(y1, y0);
            ocx = __fadd_rn(x0, __fmul_rn(otw, 0.5f));
            ocy = __fadd_rn(y0, __fmul_rn(oth, 0.5f));
        }
        float* o = out + ((size_t)b * 200 + tid) * 6;
        o[0] = cls; o[1] = score; o[2] = ocx; o[3] = ocy; o[4] = otw; o[5] = oth;
    }
}

__device__ __forceinline__ u64 pack_fk(const Cand& cd, const u32* skept, int tid) {
    // kept and within class top-300: key carries (score, ~flat, anchor)
    if (cd.valid && skept[tid] && cd.r < MC) {
        u32 flat = cd.c * MC + (u32)cd.r;
        return ((u64)cd.ub << 32) | ((u64)(0x3FFFFu ^ flat) << 14) | (u64)cd.anch;
    }
    return 0ull;
}

// ---- final: fast path (no tkey needed); inline exact fallback; self-reset ----
__global__ void __launch_bounds__(1024, 1) k_nms_final(const float* __restrict__ in,
                                                       float* __restrict__ out) {
    __shared__ u64    skey[1024];
    __shared__ u64    ssup[1024];
    __shared__ u32    sclass[1024];
    __shared__ float4 sbox[1024];
    __shared__ float  sarea[1024];
    __shared__ u32    skept[1024];
    __shared__ u32    scnt;

    int b = blockIdx.x, tid = threadIdx.x;
    u32 raw = g_ccnt[b];
    u32 n = min(raw, (u32)CAPN);

    // ---- phase A: sort collected keys desc (class desc, score desc, anchor asc) ----
    u64 p = ((u32)tid < n) ? g_col[b * CAPN + tid] : 0ull;
    sort1024_desc(p, skey, tid);

    Cand cd = extract_rank(in, b, tid, n, skey, sclass, sbox, sarea, skept);

    // fastok: >=200 distinct classes collected => kept-set superset of true top-200
    int D = __syncthreads_count(cd.valid && cd.r == 0);
    bool fastok = (D >= 200) && (raw <= (u32)CAPN);   // block-uniform

    if (!fastok) {
        // ======== exact fallback (correctness anchor; never taken in practice) ====
        float m = 0.f;
        if (tid < NCLS) {
            #pragma unroll 1
            for (int a = 0; a < NANCH; a++)
                m = fmaxf(m, __ldg(&in[((size_t)b * NANCH + a) * ROWD + 1 + tid]));
        }
        u64 pm = (tid < NCLS && m > 0.01f)
               ? (((u64)__float_as_uint(m) << 32) | (u32)(~(u32)(tid * MC))) : 0ull;
        sort1024_desc(pm, skey, tid);
        u32 th = (u32)(skey[199] >> 32);             // exact tkey-hi for collection
        __syncthreads();

        if (tid == 0) scnt = 0;
        __syncthreads();
        if (tid < NCLS) {
            #pragma unroll 1
            for (int a = 0; a < NANCH; a++) {
                float v = __ldg(&in[((size_t)b * NANCH + a) * ROWD + 1 + tid]);
                if (v > 0.01f && __float_as_uint(v) >= th) {
                    u32 pos = atomicAdd(&scnt, 1u);
                    if (pos < CAPN)
                        skey[pos] = ((u64)tid << 46) | ((u64)__float_as_uint(v) << 14)
                                  | (u64)(0x3FFFu - (u32)a);
                }
            }
        }
        __syncthreads();
        n = min(scnt, (u32)CAPN);
        u64 q = ((u32)tid < n) ? skey[tid] : 0ull;
        __syncthreads();
        sort1024_desc(q, skey, tid);
        cd = extract_rank(in, b, tid, n, skey, sclass, sbox, sarea, skept);
    }

    nms_mark(tid, n, cd, sclass, sbox, sarea, skept, ssup);
    sort_emit(in, out, b, tid, pack_fk(cd, skept, tid), skey);

    // self-reset for the next graph replay (all g_col/g_ccnt reads are done)
    if (tid == 0) g_ccnt[b] = 0;
}

// ------------------------------------------------------------------------------
extern "C" void kernel_launch(void* const* d_in, const int* in_sizes, int n_in,
                              void* d_out, int out_size) {
    const float* in = (const float*)d_in[0];
    float* out = (float*)d_out;

    k_collect<<<dim3((NANCH + 15) / 16, 2), 256>>>(in);
    k_nms_final<<<2, 1024>>>(in, out);
}

// round 14
// speedup vs baseline: 1.5526x; 1.5526x over previous
#include <cuda_runtime.h>

#define NANCH 8732
#define NCLS  599
#define MC    300
#define CAPN  1024
#define ROWD  604
#define TH_COLLECT 0.9999f

typedef unsigned int u32;
typedef unsigned long long u64;

// ------------------- static device scratch (no allocations) -------------------
__device__ u64 g_col[2 * CAPN];        // collected candidate sortkeys
__device__ u32 g_ccnt[2];              // per-image collected counters (self-resetting)

// -------- speculative collect: all scores >= TH_COLLECT, 2 anchors/warp -------
__device__ __forceinline__ void col_append(int b, u32 c, float f, u32 a) {
    u32 p = atomicAdd(&g_ccnt[b], 1u);
    if (p < CAPN)
        g_col[b * CAPN + p] =
            ((u64)c << 46) | ((u64)__float_as_uint(f) << 14) | (u64)(0x3FFFu - a);
}

__global__ void __launch_bounds__(256) k_collect(const float* __restrict__ in) {
    int b    = blockIdx.y;
    int w    = threadIdx.x >> 5, lane = threadIdx.x & 31;
    int a0   = blockIdx.x * 16 + w * 2;
    bool ok0 = a0 < NANCH, ok1 = a0 + 1 < NANCH;

    const float4* r0 = (const float4*)(in + ((size_t)b * NANCH + a0) * ROWD);
    const float4* r1 = (const float4*)(in + ((size_t)b * NANCH + a0 + 1) * ROWD);

    float4 v[5], u[5];
    #pragma unroll
    for (int i = 0; i < 5; i++) {
        int idx = lane + 32 * i;                 // 0..150 valid (151 float4/row)
        bool inr = idx < 151;
        v[i] = (ok0 && inr) ? __ldg(&r0[idx]) : make_float4(0.f, 0.f, 0.f, 0.f);
        u[i] = (ok1 && inr) ? __ldg(&r1[idx]) : make_float4(0.f, 0.f, 0.f, 0.f);
    }

    #pragma unroll
    for (int i = 0; i < 5; i++) {
        int base = 4 * (lane + 32 * i);
        float fv[4] = {v[i].x, v[i].y, v[i].z, v[i].w};
        float fu[4] = {u[i].x, u[i].y, u[i].z, u[i].w};
        #pragma unroll
        for (int s = 0; s < 4; s++) {
            int j = base + s;                    // raw column; class = j-1
            if (j >= 1 && j <= NCLS) {
                if (fv[s] >= TH_COLLECT) col_append(b, (u32)(j - 1), fv[s], (u32)a0);
                if (fu[s] >= TH_COLLECT) col_append(b, (u32)(j - 1), fu[s], (u32)(a0 + 1));
            }
        }
    }
}

// ------------- hybrid bitonic 1024 desc (shfl j<=16, smem j>=32) --------------
__device__ __forceinline__ u64 sort1024_desc(u64 p, u64* sm, int tid) {
    #pragma unroll
    for (int k = 2; k <= 32; k <<= 1)
        #pragma unroll
        for (int j = k >> 1; j; j >>= 1) {
            u64 q = __shfl_xor_sync(0xffffffffu, p, j);
            bool keep_max = ((tid & k) == 0) == ((tid & j) == 0);
            bool sw = keep_max ? (q > p) : (q < p);
            if (sw) p = q;
        }
    sm[tid] = p;
    __syncthreads();
    for (int k = 64; k <= 1024; k <<= 1) {
        for (int j = k >> 1; j >= 32; j >>= 1) {
            int x = tid ^ j;
            if (x > tid) {
                u64 a = sm[tid], bb = sm[x];
                bool sw = ((tid & k) == 0) ? (a < bb) : (a > bb);
                if (sw) { sm[tid] = bb; sm[x] = a; }
            }
            __syncthreads();
        }
        p = sm[tid];
        #pragma unroll
        for (int j = 16; j; j >>= 1) {
            u64 q = __shfl_xor_sync(0xffffffffu, p, j);
            bool keep_max = ((tid & k) == 0) == ((tid & j) == 0);
            bool sw = keep_max ? (q > p) : (q < p);
            if (sw) p = q;
        }
        sm[tid] = p;
        __syncthreads();
    }
    return p;
}

// --------------------------- shared final-stage pieces ------------------------
struct Cand { bool valid; u32 c, ub, anch; int r; };

__device__ __forceinline__ Cand extract_rank(const float* __restrict__ in, int b, int tid,
        u32 n, u64* skey, u32* sclass, float4* sbox, float* sarea, u32* skept) {
    Cand cd; cd.valid = (u32)tid < n; cd.c = 0; cd.ub = 0; cd.anch = 0; cd.r = 0;
    skept[tid] = 0;
    if (cd.valid) {
        u64 key = skey[tid];
        cd.c    = (u32)(key >> 46);
        cd.ub   = (u32)(key >> 14);
        cd.anch = 0x3FFFu - (u32)(key & 0x3FFFu);
        sclass[tid] = cd.c;
        const float4 bx = *(const float4*)(in + ((size_t)b * NANCH + cd.anch) * ROWD + 600);
        // bx = (cx, cy, w, h) -> exact reference corner encode
        float y0 = __fsub_rn(bx.y, __fmul_rn(bx.w, 0.5f));
        float x0 = __fsub_rn(bx.x, __fmul_rn(bx.z, 0.5f));
        float y1 = __fadd_rn(bx.y, __fmul_rn(bx.w, 0.5f));
        float x1 = __fadd_rn(bx.x, __fmul_rn(bx.z, 0.5f));
        sbox[tid]  = make_float4(y0, x0, y1, x1);
        sarea[tid] = __fmul_rn(__fsub_rn(y1, y0), __fsub_rn(x1, x0));
        int r = 0;
        while (tid - r - 1 >= 0 && (u32)(skey[tid - r - 1] >> 46) == cd.c) r++;
        cd.r = r;
    }
    __syncthreads();
    return cd;
}

__device__ __forceinline__ bool iou_gt45(float4 bj, float aj, float4 bk, float ak) {
    float ih = fmaxf(__fsub_rn(fminf(bj.z, bk.z), fmaxf(bj.x, bk.x)), 0.f);
    float iw = fmaxf(__fsub_rn(fminf(bj.w, bk.w), fmaxf(bj.y, bk.y)), 0.f);
    float inter = __fmul_rn(ih, iw);
    float uni   = __fsub_rn(__fadd_rn(aj, ak), inter);
    return uni > 0.f && __fdiv_rn(inter, uni) > 0.45f;
}

// serial leader greedy per class segment (segments are tiny; measured-best)
__device__ __forceinline__ void nms_mark(int tid, u32 n, const Cand& cd,
        u32* sclass, float4* sbox, float* sarea, u32* skept) {
    if (cd.valid && cd.r == 0) {                 // one leader per class segment
        skept[tid] = 1;
        for (int k = tid + 1; k < (int)n && sclass[k] == cd.c; k++) {
            float4 bk = sbox[k];
            float  ak = sarea[k];
            bool sup = false;
            for (int j = tid; j < k; j++) {
                if (skept[j] && iou_gt45(sbox[j], sarea[j], bk, ak)) { sup = true; break; }
            }
            skept[k] = sup ? 0u : 1u;
        }
    }
    __syncthreads();
}

// final key packs everything: (score, ~flat, anchor); flat<2^18, anchor<2^14
__device__ __forceinline__ u64 pack_fk(const Cand& cd, const u32* skept, int tid) {
    if (cd.valid && skept[tid] && cd.r < MC) {
        u32 flat = cd.c * MC + (u32)cd.r;
        return ((u64)cd.ub << 32) | ((u64)(0x3FFFFu ^ flat) << 14) | (u64)cd.anch;
    }
    return 0ull;
}

// sort packed final keys and emit top-200 with exact inverse transform
__device__ __forceinline__ void sort_emit(const float* __restrict__ in,
        float* __restrict__ out, int b, int tid, u64 fk, u64* skey) {
    sort1024_desc(fk, skey, tid);
    if (tid < 200) {
        u64 key = skey[tid];
        float cls = 0.f, score = 0.f, ocx = 0.f, ocy = 0.f, otw = 0.f, oth = 0.f;
        if (key) {
            score = __uint_as_float((u32)(key >> 32));
            u32 flat = 0x3FFFFu ^ ((u32)(key >> 14) & 0x3FFFFu);
            cls = (float)(flat / MC + 1);
            u32 anchor = (u32)key & 0x3FFFu;
            const float4 bx = *(const float4*)(in + ((size_t)b * NANCH + anchor) * ROWD + 600);
            float y0 = __fsub_rn(bx.y, __fmul_rn(bx.w, 0.5f));
            float x0 = __fsub_rn(bx.x, __fmul_rn(bx.z, 0.5f));
            float y1 = __fadd_rn(bx.y, __fmul_rn(bx.w, 0.5f));
            float x1 = __fadd_rn(bx.x, __fmul_rn(bx.z, 0.5f));
            otw = __fsub_rn(x1, x0);
            oth = __fsub_rn(y1, y0);
            ocx = __fadd_rn(x0, __fmul_rn(otw, 0.5f));
            ocy = __fadd_rn(y0, __fmul_rn(oth, 0.5f));
        }
        float* o = out + ((size_t)b * 200 + tid) * 6;
        o[0] = cls; o[1] = score; o[2] = ocx; o[3] = ocy; o[4] = otw; o[5] = oth;
    }
}

// ---- final: fast path (2 sorts total); inline exact fallback; self-reset ----
__global__ void __launch_bounds__(1024, 1) k_nms_final(const float* __restrict__ in,
                                                       float* __restrict__ out) {
    __shared__ u64    skey[1024];
    __shared__ u32    sclass[1024];
    __shared__ float4 sbox[1024];
    __shared__ float  sarea[1024];
    __shared__ u32    skept[1024];
    __shared__ u32    scnt;

    int b = blockIdx.x, tid = threadIdx.x;
    u32 raw = g_ccnt[b];
    u32 n = min(raw, (u32)CAPN);

    // ---- phase A: sort collected keys desc (class desc, score desc, anchor asc) ----
    u64 p = ((u32)tid < n) ? g_col[b * CAPN + tid] : 0ull;
    sort1024_desc(p, skey, tid);

    Cand cd = extract_rank(in, b, tid, n, skey, sclass, sbox, sarea, skept);

    // fastok: >=200 distinct classes collected => kept-set superset of true top-200
    int D = __syncthreads_count(cd.valid && cd.r == 0);
    bool fastok = (D >= 200) && (raw <= (u32)CAPN);   // block-uniform

    if (!fastok) {
        // ======== exact fallback (correctness anchor; never taken in practice) ====
        float m = 0.f;
        if (tid < NCLS) {
            #pragma unroll 1
            for (int a = 0; a < NANCH; a++)
                m = fmaxf(m, __ldg(&in[((size_t)b * NANCH + a) * ROWD + 1 + tid]));
        }
        u64 pm = (tid < NCLS && m > 0.01f)
               ? (((u64)__float_as_uint(m) << 32) | (u32)(~(u32)(tid * MC))) : 0ull;
        sort1024_desc(pm, skey, tid);
        u32 th = (u32)(skey[199] >> 32);             // exact tkey-hi for collection
        __syncthreads();

        if (tid == 0) scnt = 0;
        __syncthreads();
        if (tid < NCLS) {
            #pragma unroll 1
            for (int a = 0; a < NANCH; a++) {
                float v = __ldg(&in[((size_t)b * NANCH + a) * ROWD + 1 + tid]);
                if (v > 0.01f && __float_as_uint(v) >= th) {
                    u32 pos = atomicAdd(&scnt, 1u);
                    if (pos < CAPN)
                        skey[pos] = ((u64)tid << 46) | ((u64)__float_as_uint(v) << 14)
                                  | (u64)(0x3FFFu - (u32)a);
                }
            }
        }
        __syncthreads();
        n = min(scnt, (u32)CAPN);
        u64 q = ((u32)tid < n) ? skey[tid] : 0ull;
        __syncthreads();
        sort1024_desc(q, skey, tid);
        cd = extract_rank(in, b, tid, n, skey, sclass, sbox, sarea, skept);
    }

    nms_mark(tid, n, cd, sclass, sbox, sarea, skept);
    sort_emit(in, out, b, tid, pack_fk(cd, skept, tid), skey);

    // self-reset for the next graph replay (all g_col/g_ccnt reads are done)
    if (tid == 0) g_ccnt[b] = 0;
}

// ------------------------------------------------------------------------------
extern "C" void kernel_launch(void* const* d_in, const int* in_sizes, int n_in,
                              void* d_out, int out_size) {
    const float* in = (const float*)d_in[0];
    float* out = (float*)d_out;

    k_collect<<<dim3((NANCH + 15) / 16, 2), 256>>>(in);
    k_nms_final<<<2, 1024>>>(in, out);
}

// round 15
// speedup vs baseline: 1.8458x; 1.1889x over previous
#include <cuda_runtime.h>

#define NANCH 8732
#define NCLS  599
#define MC    300
#define CAPN  1024
#define ROWD  604
#define TH_COLLECT 0.9999f

typedef unsigned int u32;
typedef unsigned long long u64;

// ------------------- static device scratch (no allocations) -------------------
__device__ u64 g_col[2 * CAPN];        // collected candidate sortkeys
__device__ u32 g_ccnt[2];              // per-image collected counters (self-resetting)

// -------- speculative collect: all scores >= TH_COLLECT, 2 anchors/warp -------
__device__ __forceinline__ void col_append(int b, u32 c, float f, u32 a) {
    u32 p = atomicAdd(&g_ccnt[b], 1u);
    if (p < CAPN)
        g_col[b * CAPN + p] =
            ((u64)c << 46) | ((u64)__float_as_uint(f) << 14) | (u64)(0x3FFFu - a);
}

__global__ void __launch_bounds__(256) k_collect(const float* __restrict__ in) {
    int b    = blockIdx.y;
    int w    = threadIdx.x >> 5, lane = threadIdx.x & 31;
    int a0   = blockIdx.x * 16 + w * 2;
    bool ok0 = a0 < NANCH, ok1 = a0 + 1 < NANCH;

    const float4* r0 = (const float4*)(in + ((size_t)b * NANCH + a0) * ROWD);
    const float4* r1 = (const float4*)(in + ((size_t)b * NANCH + a0 + 1) * ROWD);

    float4 v[5], u[5];
    #pragma unroll
    for (int i = 0; i < 5; i++) {
        int idx = lane + 32 * i;                 // 0..150 valid (151 float4/row)
        bool inr = idx < 151;
        v[i] = (ok0 && inr) ? __ldg(&r0[idx]) : make_float4(0.f, 0.f, 0.f, 0.f);
        u[i] = (ok1 && inr) ? __ldg(&r1[idx]) : make_float4(0.f, 0.f, 0.f, 0.f);
    }

    #pragma unroll
    for (int i = 0; i < 5; i++) {
        int base = 4 * (lane + 32 * i);
        float fv[4] = {v[i].x, v[i].y, v[i].z, v[i].w};
        float fu[4] = {u[i].x, u[i].y, u[i].z, u[i].w};
        #pragma unroll
        for (int s = 0; s < 4; s++) {
            int j = base + s;                    // raw column; class = j-1
            if (j >= 1 && j <= NCLS) {
                if (fv[s] >= TH_COLLECT) col_append(b, (u32)(j - 1), fv[s], (u32)a0);
                if (fu[s] >= TH_COLLECT) col_append(b, (u32)(j - 1), fu[s], (u32)(a0 + 1));
            }
        }
    }
}

// ------------- hybrid bitonic 1024 desc (shfl j<=16, smem j>=32) --------------
__device__ __forceinline__ u64 sort1024_desc(u64 p, u64* sm, int tid) {
    #pragma unroll
    for (int k = 2; k <= 32; k <<= 1)
        #pragma unroll
        for (int j = k >> 1; j; j >>= 1) {
            u64 q = __shfl_xor_sync(0xffffffffu, p, j);
            bool keep_max = ((tid & k) == 0) == ((tid & j) == 0);
            bool sw = keep_max ? (q > p) : (q < p);
            if (sw) p = q;
        }
    sm[tid] = p;
    __syncthreads();
    for (int k = 64; k <= 1024; k <<= 1) {
        for (int j = k >> 1; j >= 32; j >>= 1) {
            int x = tid ^ j;
            if (x > tid) {
                u64 a = sm[tid], bb = sm[x];
                bool sw = ((tid & k) == 0) ? (a < bb) : (a > bb);
                if (sw) { sm[tid] = bb; sm[x] = a; }
            }
            __syncthreads();
        }
        p = sm[tid];
        #pragma unroll
        for (int j = 16; j; j >>= 1) {
            u64 q = __shfl_xor_sync(0xffffffffu, p, j);
            bool keep_max = ((tid & k) == 0) == ((tid & j) == 0);
            bool sw = keep_max ? (q > p) : (q < p);
            if (sw) p = q;
        }
        sm[tid] = p;
        __syncthreads();
    }
    return p;
}

// --------------------------- shared final-stage pieces ------------------------
struct Cand { bool valid; u32 c, ub, anch; int r; };

// fallback-only: derive rank by backward scan after a full sort
__device__ __forceinline__ Cand extract_rank(const float* __restrict__ in, int b, int tid,
        u32 n, u64* skey, u32* sclass, float4* sbox, float* sarea, u32* skept) {
    Cand cd; cd.valid = (u32)tid < n; cd.c = 0; cd.ub = 0; cd.anch = 0; cd.r = 0;
    skept[tid] = 0;
    if (cd.valid) {
        u64 key = skey[tid];
        cd.c    = (u32)(key >> 46);
        cd.ub   = (u32)(key >> 14);
        cd.anch = 0x3FFFu - (u32)(key & 0x3FFFu);
        sclass[tid] = cd.c;
        const float4 bx = *(const float4*)(in + ((size_t)b * NANCH + cd.anch) * ROWD + 600);
        float y0 = __fsub_rn(bx.y, __fmul_rn(bx.w, 0.5f));
        float x0 = __fsub_rn(bx.x, __fmul_rn(bx.z, 0.5f));
        float y1 = __fadd_rn(bx.y, __fmul_rn(bx.w, 0.5f));
        float x1 = __fadd_rn(bx.x, __fmul_rn(bx.z, 0.5f));
        sbox[tid]  = make_float4(y0, x0, y1, x1);
        sarea[tid] = __fmul_rn(__fsub_rn(y1, y0), __fsub_rn(x1, x0));
        int r = 0;
        while (tid - r - 1 >= 0 && (u32)(skey[tid - r - 1] >> 46) == cd.c) r++;
        cd.r = r;
    }
    __syncthreads();
    return cd;
}

__device__ __forceinline__ bool iou_gt45(float4 bj, float aj, float4 bk, float ak) {
    float ih = fmaxf(__fsub_rn(fminf(bj.z, bk.z), fmaxf(bj.x, bk.x)), 0.f);
    float iw = fmaxf(__fsub_rn(fminf(bj.w, bk.w), fmaxf(bj.y, bk.y)), 0.f);
    float inter = __fmul_rn(ih, iw);
    float uni   = __fsub_rn(__fadd_rn(aj, ak), inter);
    return uni > 0.f && __fdiv_rn(inter, uni) > 0.45f;
}

// serial leader greedy per class segment (segments are tiny; measured-best)
__device__ __forceinline__ void nms_mark(int tid, u32 n, const Cand& cd,
        u32* sclass, float4* sbox, float* sarea, u32* skept) {
    if (cd.valid && cd.r == 0) {                 // one leader per class segment
        skept[tid] = 1;
        for (int k = tid + 1; k < (int)n && sclass[k] == cd.c; k++) {
            float4 bk = sbox[k];
            float  ak = sarea[k];
            bool sup = false;
            for (int j = tid; j < k; j++) {
                if (skept[j] && iou_gt45(sbox[j], sarea[j], bk, ak)) { sup = true; break; }
            }
            skept[k] = sup ? 0u : 1u;
        }
    }
    __syncthreads();
}

// final key packs everything: (score, ~flat, anchor); flat<2^18, anchor<2^14
__device__ __forceinline__ u64 pack_fk(const Cand& cd, const u32* skept, int tid) {
    if (cd.valid && skept[tid] && cd.r < MC) {
        u32 flat = cd.c * MC + (u32)cd.r;
        return ((u64)cd.ub << 32) | ((u64)(0x3FFFFu ^ flat) << 14) | (u64)cd.anch;
    }
    return 0ull;
}

// sort packed final keys and emit top-200 with exact inverse transform
__device__ __forceinline__ void sort_emit(const float* __restrict__ in,
        float* __restrict__ out, int b, int tid, u64 fk, u64* skey) {
    sort1024_desc(fk, skey, tid);
    if (tid < 200) {
        u64 key = skey[tid];
        float cls = 0.f, score = 0.f, ocx = 0.f, ocy = 0.f, otw = 0.f, oth = 0.f;
        if (key) {
            score = __uint_as_float((u32)(key >> 32));
            u32 flat = 0x3FFFFu ^ ((u32)(key >> 14) & 0x3FFFFu);
            cls = (float)(flat / MC + 1);
            u32 anchor = (u32)key & 0x3FFFu;
            const float4 bx = *(const float4*)(in + ((size_t)b * NANCH + anchor) * ROWD + 600);
            float y0 = __fsub_rn(bx.y, __fmul_rn(bx.w, 0.5f));
            float x0 = __fsub_rn(bx.x, __fmul_rn(bx.z, 0.5f));
            float y1 = __fadd_rn(bx.y, __fmul_rn(bx.w, 0.5f));
            float x1 = __fadd_rn(bx.x, __fmul_rn(bx.z, 0.5f));
            otw = __fsub_rn(x1, x0);
            oth = __fsub_rn(y1, y0);
            ocx = __fadd_rn(x0, __fmul_rn(otw, 0.5f));
            ocy = __fadd_rn(y0, __fmul_rn(oth, 0.5f));
        }
        float* o = out + ((size_t)b * 200 + tid) * 6;
        o[0] = cls; o[1] = score; o[2] = ocx; o[3] = ocy; o[4] = otw; o[5] = oth;
    }
}

// ---- final: counting-sort fast path; inline exact fallback; self-reset ----
__global__ void __launch_bounds__(1024, 1) k_nms_final(const float* __restrict__ in,
                                                       float* __restrict__ out) {
    __shared__ u64    skey[1024];
    __shared__ u32    sclass[1024];
    __shared__ float4 sbox[1024];
    __shared__ float  sarea[1024];
    __shared__ u32    skept[1024];
    __shared__ u32    hist[NCLS + 1];
    __shared__ u32    sbase[NCLS + 1];
    __shared__ u32    wsum[32];
    __shared__ u32    scnt;

    int b = blockIdx.x, tid = threadIdx.x;
    int lane = tid & 31, wid = tid >> 5;
    u32 raw = g_ccnt[b];
    u32 n = min(raw, (u32)CAPN);

    // ======== phase A: counting sort by class (O(n), ~5 barriers) ========
    u64 myk = ((u32)tid < n) ? g_col[b * CAPN + tid] : 0ull;
    u32 myc = (u32)(myk >> 46);
    if (tid <= NCLS) hist[tid] = 0;
    skey[tid] = 0;
    __syncthreads();
    if ((u32)tid < n) atomicAdd(&hist[myc], 1u);
    __syncthreads();

    // exclusive scan over 600 bins: warp shfl scan + warp-total scan
    u32 cnt0 = (tid <= NCLS) ? hist[tid] : 0;
    u32 inc = cnt0;
    #pragma unroll
    for (int off = 1; off < 32; off <<= 1) {
        u32 o = __shfl_up_sync(0xffffffffu, inc, off);
        if (lane >= off) inc += o;
    }
    if (wid < 20 && lane == 31) wsum[wid] = inc;
    __syncthreads();
    if (tid < 32) {
        u32 wv = (tid < 20) ? wsum[tid] : 0;
        #pragma unroll
        for (int off = 1; off < 32; off <<= 1) {
            u32 o = __shfl_up_sync(0xffffffffu, wv, off);
            if (lane >= off) wv += o;
        }
        wsum[tid] = wv;                          // inclusive warp totals
    }
    __syncthreads();
    if (tid <= NCLS) {
        u32 woffs = (wid > 0) ? wsum[wid - 1] : 0;
        sbase[tid] = woffs + inc - cnt0;         // exclusive prefix
        hist[tid] = 0;                           // reuse as scatter cursor
    }
    __syncthreads();

    if ((u32)tid < n) {
        u32 pos = sbase[myc] + atomicAdd(&hist[myc], 1u);
        skey[pos] = myk;
    }
    __syncthreads();

    // per-segment insertion sort desc by leader (segments are tiny; keys unique)
    {
        u64 kk = skey[tid];
        u32 c2 = (u32)(kk >> 46);
        if ((u32)tid < n && tid == (int)sbase[c2]) {
            int len = (int)hist[c2];
            for (int i = 1; i < len; i++) {
                u64 v = skey[tid + i];
                int j = i - 1;
                while (j >= 0 && skey[tid + j] < v) { skey[tid + j + 1] = skey[tid + j]; j--; }
                skey[tid + j + 1] = v;
            }
        }
    }
    __syncthreads();

    // extract fields, rank = tid - segment base, load boxes
    Cand cd; cd.valid = (u32)tid < n; cd.c = 0; cd.ub = 0; cd.anch = 0; cd.r = 0;
    skept[tid] = 0;
    if (cd.valid) {
        u64 key = skey[tid];
        cd.c    = (u32)(key >> 46);
        cd.ub   = (u32)(key >> 14);
        cd.anch = 0x3FFFu - (u32)(key & 0x3FFFu);
        cd.r    = tid - (int)sbase[cd.c];
        sclass[tid] = cd.c;
        const float4 bx = *(const float4*)(in + ((size_t)b * NANCH + cd.anch) * ROWD + 600);
        float y0 = __fsub_rn(bx.y, __fmul_rn(bx.w, 0.5f));
        float x0 = __fsub_rn(bx.x, __fmul_rn(bx.z, 0.5f));
        float y1 = __fadd_rn(bx.y, __fmul_rn(bx.w, 0.5f));
        float x1 = __fadd_rn(bx.x, __fmul_rn(bx.z, 0.5f));
        sbox[tid]  = make_float4(y0, x0, y1, x1);
        sarea[tid] = __fmul_rn(__fsub_rn(y1, y0), __fsub_rn(x1, x0));
    }
    __syncthreads();

    // fastok: >=200 distinct classes collected => kept-set superset of true top-200
    int D = __syncthreads_count(cd.valid && cd.r == 0);
    bool fastok = (D >= 200) && (raw <= (u32)CAPN);   // block-uniform

    if (!fastok) {
        // ======== exact fallback (correctness anchor; never taken in practice) ====
        float m = 0.f;
        if (tid < NCLS) {
            #pragma unroll 1
            for (int a = 0; a < NANCH; a++)
                m = fmaxf(m, __ldg(&in[((size_t)b * NANCH + a) * ROWD + 1 + tid]));
        }
        u64 pm = (tid < NCLS && m > 0.01f)
               ? (((u64)__float_as_uint(m) << 32) | (u32)(~(u32)(tid * MC))) : 0ull;
        sort1024_desc(pm, skey, tid);
        u32 th = (u32)(skey[199] >> 32);             // exact tkey-hi for collection
        __syncthreads();

        if (tid == 0) scnt = 0;
        __syncthreads();
        if (tid < NCLS) {
            #pragma unroll 1
            for (int a = 0; a < NANCH; a++) {
                float v = __ldg(&in[((size_t)b * NANCH + a) * ROWD + 1 + tid]);
                if (v > 0.01f && __float_as_uint(v) >= th) {
                    u32 pos = atomicAdd(&scnt, 1u);
                    if (pos < CAPN)
                        skey[pos] = ((u64)tid << 46) | ((u64)__float_as_uint(v) << 14)
                                  | (u64)(0x3FFFu - (u32)a);
                }
            }
        }
        __syncthreads();
        n = min(scnt, (u32)CAPN);
        u64 q = ((u32)tid < n) ? skey[tid] : 0ull;
        __syncthreads();
        sort1024_desc(q, skey, tid);
        cd = extract_rank(in, b, tid, n, skey, sclass, sbox, sarea, skept);
    }

    nms_mark(tid, n, cd, sclass, sbox, sarea, skept);
    sort_emit(in, out, b, tid, pack_fk(cd, skept, tid), skey);

    // self-reset for the next graph replay (all g_col/g_ccnt reads are done)
    if (tid == 0) g_ccnt[b] = 0;
}

// ------------------------------------------------------------------------------
extern "C" void kernel_launch(void* const* d_in, const int* in_sizes, int n_in,
                              void* d_out, int out_size) {
    const float* in = (const float*)d_in[0];
    float* out = (float*)d_out;

    k_collect<<<dim3((NANCH + 15) / 16, 2), 256>>>(in);
    k_nms_final<<<2, 1024>>>(in, out);
}

// round 16
// speedup vs baseline: 2.2187x; 1.2020x over previous
#include <cuda_runtime.h>

#define NANCH 8732
#define NCLS  599
#define MC    300
#define CAPN  1024
#define ROWD  604
#define TH_COLLECT 0.9999f

typedef unsigned int u32;
typedef unsigned long long u64;

// ------------------- static device scratch (no allocations) -------------------
__device__ u64 g_col[2 * CAPN];        // collected candidate sortkeys
__device__ u32 g_ccnt[2];              // per-image collected counters (self-resetting)

// -------- speculative collect: all scores >= TH_COLLECT, 2 anchors/warp -------
__device__ __forceinline__ void col_append(int b, u32 c, float f, u32 a) {
    u32 p = atomicAdd(&g_ccnt[b], 1u);
    if (p < CAPN)
        g_col[b * CAPN + p] =
            ((u64)c << 46) | ((u64)__float_as_uint(f) << 14) | (u64)(0x3FFFu - a);
}

__global__ void __launch_bounds__(256) k_collect(const float* __restrict__ in) {
    int b    = blockIdx.y;
    int w    = threadIdx.x >> 5, lane = threadIdx.x & 31;
    int a0   = blockIdx.x * 16 + w * 2;
    bool ok0 = a0 < NANCH, ok1 = a0 + 1 < NANCH;

    const float4* r0 = (const float4*)(in + ((size_t)b * NANCH + a0) * ROWD);
    const float4* r1 = (const float4*)(in + ((size_t)b * NANCH + a0 + 1) * ROWD);

    float4 v[5], u[5];
    #pragma unroll
    for (int i = 0; i < 5; i++) {
        int idx = lane + 32 * i;                 // 0..150 valid (151 float4/row)
        bool inr = idx < 151;
        v[i] = (ok0 && inr) ? __ldg(&r0[idx]) : make_float4(0.f, 0.f, 0.f, 0.f);
        u[i] = (ok1 && inr) ? __ldg(&r1[idx]) : make_float4(0.f, 0.f, 0.f, 0.f);
    }

    #pragma unroll
    for (int i = 0; i < 5; i++) {
        int base = 4 * (lane + 32 * i);
        float fv[4] = {v[i].x, v[i].y, v[i].z, v[i].w};
        float fu[4] = {u[i].x, u[i].y, u[i].z, u[i].w};
        #pragma unroll
        for (int s = 0; s < 4; s++) {
            int j = base + s;                    // raw column; class = j-1
            if (j >= 1 && j <= NCLS) {
                if (fv[s] >= TH_COLLECT) col_append(b, (u32)(j - 1), fv[s], (u32)a0);
                if (fu[s] >= TH_COLLECT) col_append(b, (u32)(j - 1), fu[s], (u32)(a0 + 1));
            }
        }
    }
}

// ---- hybrid bitonic W desc (W in {256,512,1024}, block-uniform; all sync) ----
__device__ __forceinline__ void sortW_desc(u64 p, u64* sm, int tid, int W) {
    if (tid < W) {
        #pragma unroll
        for (int k = 2; k <= 32; k <<= 1)
            #pragma unroll
            for (int j = k >> 1; j; j >>= 1) {
                u64 q = __shfl_xor_sync(0xffffffffu, p, j);
                bool keep_max = ((tid & k) == 0) == ((tid & j) == 0);
                bool sw = keep_max ? (q > p) : (q < p);
                if (sw) p = q;
            }
        sm[tid] = p;
    }
    __syncthreads();
    for (int k = 64; k <= W; k <<= 1) {
        for (int j = k >> 1; j >= 32; j >>= 1) {
            if (tid < W) {
                int x = tid ^ j;
                if (x > tid) {
                    u64 a = sm[tid], bb = sm[x];
                    bool sw = ((tid & k) == 0) ? (a < bb) : (a > bb);
                    if (sw) { sm[tid] = bb; sm[x] = a; }
                }
            }
            __syncthreads();
        }
        if (tid < W) {
            p = sm[tid];
            #pragma unroll
            for (int j = 16; j; j >>= 1) {
                u64 q = __shfl_xor_sync(0xffffffffu, p, j);
                bool keep_max = ((tid & k) == 0) == ((tid & j) == 0);
                bool sw = keep_max ? (q > p) : (q < p);
                if (sw) p = q;
            }
            sm[tid] = p;
        }
        __syncthreads();
    }
}

// --------------------------- shared final-stage pieces ------------------------
struct Cand { bool valid; u32 c, ub, anch; int r; };

// fallback-only: derive rank by backward scan after a full sort
__device__ __forceinline__ Cand extract_rank(const float* __restrict__ in, int b, int tid,
        u32 n, u64* skey, u32* sclass, float4* sbox, float* sarea, u32* skept) {
    Cand cd; cd.valid = (u32)tid < n; cd.c = 0; cd.ub = 0; cd.anch = 0; cd.r = 0;
    skept[tid] = 0;
    if (cd.valid) {
        u64 key = skey[tid];
        cd.c    = (u32)(key >> 46);
        cd.ub   = (u32)(key >> 14);
        cd.anch = 0x3FFFu - (u32)(key & 0x3FFFu);
        sclass[tid] = cd.c;
        const float4 bx = *(const float4*)(in + ((size_t)b * NANCH + cd.anch) * ROWD + 600);
        float y0 = __fsub_rn(bx.y, __fmul_rn(bx.w, 0.5f));
        float x0 = __fsub_rn(bx.x, __fmul_rn(bx.z, 0.5f));
        float y1 = __fadd_rn(bx.y, __fmul_rn(bx.w, 0.5f));
        float x1 = __fadd_rn(bx.x, __fmul_rn(bx.z, 0.5f));
        sbox[tid]  = make_float4(y0, x0, y1, x1);
        sarea[tid] = __fmul_rn(__fsub_rn(y1, y0), __fsub_rn(x1, x0));
        int r = 0;
        while (tid - r - 1 >= 0 && (u32)(skey[tid - r - 1] >> 46) == cd.c) r++;
        cd.r = r;
    }
    __syncthreads();
    return cd;
}

__device__ __forceinline__ bool iou_gt45(float4 bj, float aj, float4 bk, float ak) {
    float ih = fmaxf(__fsub_rn(fminf(bj.z, bk.z), fmaxf(bj.x, bk.x)), 0.f);
    float iw = fmaxf(__fsub_rn(fminf(bj.w, bk.w), fmaxf(bj.y, bk.y)), 0.f);
    float inter = __fmul_rn(ih, iw);
    float uni   = __fsub_rn(__fadd_rn(aj, ak), inter);
    return uni > 0.f && __fdiv_rn(inter, uni) > 0.45f;
}

// serial leader greedy per class segment (segments are tiny; measured-best)
__device__ __forceinline__ void nms_mark(int tid, u32 n, const Cand& cd,
        u32* sclass, float4* sbox, float* sarea, u32* skept) {
    if (cd.valid && cd.r == 0) {                 // one leader per class segment
        skept[tid] = 1;
        for (int k = tid + 1; k < (int)n && sclass[k] == cd.c; k++) {
            float4 bk = sbox[k];
            float  ak = sarea[k];
            bool sup = false;
            for (int j = tid; j < k; j++) {
                if (skept[j] && iou_gt45(sbox[j], sarea[j], bk, ak)) { sup = true; break; }
            }
            skept[k] = sup ? 0u : 1u;
        }
    }
    __syncthreads();
}

// final key packs everything: (score, ~flat, anchor); flat<2^18, anchor<2^14
__device__ __forceinline__ u64 pack_fk(const Cand& cd, const u32* skept, int tid) {
    if (cd.valid && skept[tid] && cd.r < MC) {
        u32 flat = cd.c * MC + (u32)cd.r;
        return ((u64)cd.ub << 32) | ((u64)(0x3FFFFu ^ flat) << 14) | (u64)cd.anch;
    }
    return 0ull;
}

// emit top-200 (skey sorted desc) with exact inverse transform
__device__ __forceinline__ void emit200(const float* __restrict__ in,
        float* __restrict__ out, int b, int tid, const u64* skey) {
    if (tid < 200) {
        u64 key = skey[tid];
        float cls = 0.f, score = 0.f, ocx = 0.f, ocy = 0.f, otw = 0.f, oth = 0.f;
        if (key) {
            score = __uint_as_float((u32)(key >> 32));
            u32 flat = 0x3FFFFu ^ ((u32)(key >> 14) & 0x3FFFFu);
            cls = (float)(flat / MC + 1);
            u32 anchor = (u32)key & 0x3FFFu;
            const float4 bx = *(const float4*)(in + ((size_t)b * NANCH + anchor) * ROWD + 600);
            float y0 = __fsub_rn(bx.y, __fmul_rn(bx.w, 0.5f));
            float x0 = __fsub_rn(bx.x, __fmul_rn(bx.z, 0.5f));
            float y1 = __fadd_rn(bx.y, __fmul_rn(bx.w, 0.5f));
            float x1 = __fadd_rn(bx.x, __fmul_rn(bx.z, 0.5f));
            otw = __fsub_rn(x1, x0);
            oth = __fsub_rn(y1, y0);
            ocx = __fadd_rn(x0, __fmul_rn(otw, 0.5f));
            ocy = __fadd_rn(y0, __fmul_rn(oth, 0.5f));
        }
        float* o = out + ((size_t)b * 200 + tid) * 6;
        o[0] = cls; o[1] = score; o[2] = ocx; o[3] = ocy; o[4] = otw; o[5] = oth;
    }
}

// ---- final: counting-sort + pruned final sort; inline exact fallback ----
__global__ void __launch_bounds__(1024, 1) k_nms_final(const float* __restrict__ in,
                                                       float* __restrict__ out) {
    __shared__ u64    skey[1024];
    __shared__ u32    sclass[1024];
    __shared__ float4 sbox[1024];
    __shared__ float  sarea[1024];
    __shared__ u32    skept[1024];
    __shared__ u32    hist[NCLS + 1];
    __shared__ u32    sbase[NCLS + 1];
    __shared__ u32    wsum[32];
    __shared__ u32    scnt, s_cut, s_sel, s_K;

    int b = blockIdx.x, tid = threadIdx.x;
    int lane = tid & 31, wid = tid >> 5;
    u32 raw = g_ccnt[b];
    u32 n = min(raw, (u32)CAPN);

    // ======== phase A: counting sort by class (O(n)) ========
    u64 myk = ((u32)tid < n) ? g_col[b * CAPN + tid] : 0ull;
    u32 myc = (u32)(myk >> 46);
    if (tid <= NCLS) hist[tid] = 0;
    skey[tid] = 0;
    __syncthreads();
    if ((u32)tid < n) atomicAdd(&hist[myc], 1u);
    __syncthreads();

    // exclusive scan over 600 bins: warp shfl scan + warp-total scan
    u32 cnt0 = (tid <= NCLS) ? hist[tid] : 0;
    u32 inc = cnt0;
    #pragma unroll
    for (int off = 1; off < 32; off <<= 1) {
        u32 o = __shfl_up_sync(0xffffffffu, inc, off);
        if (lane >= off) inc += o;
    }
    if (wid < 20 && lane == 31) wsum[wid] = inc;
    __syncthreads();
    if (tid < 32) {
        u32 wv = (tid < 20) ? wsum[tid] : 0;
        #pragma unroll
        for (int off = 1; off < 32; off <<= 1) {
            u32 o = __shfl_up_sync(0xffffffffu, wv, off);
            if (lane >= off) wv += o;
        }
        wsum[tid] = wv;                          // inclusive warp totals
    }
    __syncthreads();
    if (tid <= NCLS) {
        u32 woffs = (wid > 0) ? wsum[wid - 1] : 0;
        sbase[tid] = woffs + inc - cnt0;         // exclusive prefix
        hist[tid] = 0;                           // reuse as scatter cursor
    }
    __syncthreads();

    if ((u32)tid < n) {
        u32 pos = sbase[myc] + atomicAdd(&hist[myc], 1u);
        skey[pos] = myk;
    }
    __syncthreads();

    // per-segment insertion sort desc by leader (segments are tiny; keys unique)
    {
        u64 kk = skey[tid];
        u32 c2 = (u32)(kk >> 46);
        if ((u32)tid < n && tid == (int)sbase[c2]) {
            int len = (int)hist[c2];
            for (int i = 1; i < len; i++) {
                u64 v = skey[tid + i];
                int j = i - 1;
                while (j >= 0 && skey[tid + j] < v) { skey[tid + j + 1] = skey[tid + j]; j--; }
                skey[tid + j + 1] = v;
            }
        }
    }
    __syncthreads();

    // extract fields, rank = tid - segment base, load boxes
    Cand cd; cd.valid = (u32)tid < n; cd.c = 0; cd.ub = 0; cd.anch = 0; cd.r = 0;
    skept[tid] = 0;
    if (cd.valid) {
        u64 key = skey[tid];
        cd.c    = (u32)(key >> 46);
        cd.ub   = (u32)(key >> 14);
        cd.anch = 0x3FFFu - (u32)(key & 0x3FFFu);
        cd.r    = tid - (int)sbase[cd.c];
        sclass[tid] = cd.c;
        const float4 bx = *(const float4*)(in + ((size_t)b * NANCH + cd.anch) * ROWD + 600);
        float y0 = __fsub_rn(bx.y, __fmul_rn(bx.w, 0.5f));
        float x0 = __fsub_rn(bx.x, __fmul_rn(bx.z, 0.5f));
        float y1 = __fadd_rn(bx.y, __fmul_rn(bx.w, 0.5f));
        float x1 = __fadd_rn(bx.x, __fmul_rn(bx.z, 0.5f));
        sbox[tid]  = make_float4(y0, x0, y1, x1);
        sarea[tid] = __fmul_rn(__fsub_rn(y1, y0), __fsub_rn(x1, x0));
    }
    __syncthreads();

    // fastok: >=200 distinct classes collected => kept-set superset of true top-200
    int D = __syncthreads_count(cd.valid && cd.r == 0);
    bool fastok = (D >= 200) && (raw <= (u32)CAPN);   // block-uniform

    if (fastok) {
        nms_mark(tid, n, cd, sclass, sbox, sarea, skept);
        u64 fk = pack_fk(cd, skept, tid);

        // ---- score-histogram prune: find cutbin s.t. suffix count >= 200 ----
        const u32 BMIN = 0x3F7FE000u;            // below all fast-path score bits
        int bin = -1;
        if (fk) {
            u32 sb2 = (u32)(fk >> 32);
            u32 d2 = (sb2 >= BMIN) ? ((sb2 - BMIN) >> 4) : 0u;
            bin = (int)min(d2, 511u);
        }
        if (tid < 512) hist[tid] = 0;
        if (tid == 0) { s_cut = 0; s_sel = 0; s_K = 0; scnt = 0; }
        __syncthreads();
        if (fk) atomicAdd(&hist[bin], 1u);
        __syncthreads();
        u32 cnt2 = (tid < 512) ? hist[tid] : 0;
        u32 inc2 = cnt2;
        #pragma unroll
        for (int off = 1; off < 32; off <<= 1) {
            u32 o = __shfl_up_sync(0xffffffffu, inc2, off);
            if (lane >= off) inc2 += o;
        }
        if (wid < 16 && lane == 31) wsum[wid] = inc2;
        __syncthreads();
        if (tid < 32) {
            u32 wv = (tid < 16) ? wsum[tid] : 0;
            #pragma unroll
            for (int off = 1; off < 32; off <<= 1) {
                u32 o = __shfl_up_sync(0xffffffffu, wv, off);
                if (lane >= off) wv += o;
            }
            wsum[tid] = wv;
        }
        __syncthreads();
        u32 incl = 0;
        if (tid < 512) {
            incl = ((wid > 0) ? wsum[wid - 1] : 0) + inc2;   // inclusive prefix
            if (tid == 511) s_K = incl;
        }
        __syncthreads();
        if (tid < 512) {
            u32 K = s_K;
            u32 suff = K - (incl - cnt2);        // count of keys with bin >= tid
            if (suff >= 200 && suff - cnt2 < 200) { s_cut = (u32)tid; s_sel = suff; }
        }
        if (tid == 0 && s_K < 200) { s_cut = 0; s_sel = s_K; }
        __syncthreads();

        // ---- compact selected keys (order-free; sort restores exact order) ----
        u64* cbuf = (u64*)sbox;                  // sbox dead after pack_fk
        if (fk && bin >= (int)s_cut) cbuf[atomicAdd(&scnt, 1u)] = fk;
        __syncthreads();
        u32 sel = scnt;
        int W = (sel <= 256) ? 256 : (sel <= 512) ? 512 : 1024;
        u64 p2 = ((u32)tid < sel) ? cbuf[tid] : 0ull;
        sortW_desc(p2, skey, tid, W);
        emit200(in, out, b, tid, skey);
    } else {
        // ======== exact fallback (correctness anchor; never taken in practice) ====
        float m = 0.f;
        if (tid < NCLS) {
            #pragma unroll 1
            for (int a = 0; a < NANCH; a++)
                m = fmaxf(m, __ldg(&in[((size_t)b * NANCH + a) * ROWD + 1 + tid]));
        }
        u64 pm = (tid < NCLS && m > 0.01f)
               ? (((u64)__float_as_uint(m) << 32) | (u32)(~(u32)(tid * MC))) : 0ull;
        sortW_desc(pm, skey, tid, 1024);
        u32 th = (u32)(skey[199] >> 32);             // exact tkey-hi for collection
        __syncthreads();

        if (tid == 0) scnt = 0;
        __syncthreads();
        if (tid < NCLS) {
            #pragma unroll 1
            for (int a = 0; a < NANCH; a++) {
                float v = __ldg(&in[((size_t)b * NANCH + a) * ROWD + 1 + tid]);
                if (v > 0.01f && __float_as_uint(v) >= th) {
                    u32 pos = atomicAdd(&scnt, 1u);
                    if (pos < CAPN)
                        skey[pos] = ((u64)tid << 46) | ((u64)__float_as_uint(v) << 14)
                                  | (u64)(0x3FFFu - (u32)a);
                }
            }
        }
        __syncthreads();
        n = min(scnt, (u32)CAPN);
        u64 q = ((u32)tid < n) ? skey[tid] : 0ull;
        __syncthreads();
        sortW_desc(q, skey, tid, 1024);
        cd = extract_rank(in, b, tid, n, skey, sclass, sbox, sarea, skept);
        nms_mark(tid, n, cd, sclass, sbox, sarea, skept);
        u64 fk = pack_fk(cd, skept, tid);
        __syncthreads();                             // skey readers done
        sortW_desc(fk, skey, tid, 1024);
        emit200(in, out, b, tid, skey);
    }

    // self-reset for the next graph replay (all g_col/g_ccnt reads are done)
    if (tid == 0) g_ccnt[b] = 0;
}

// ------------------------------------------------------------------------------
extern "C" void kernel_launch(void* const* d_in, const int* in_sizes, int n_in,
                              void* d_out, int out_size) {
    const float* in = (const float*)d_in[0];
    float* out = (float*)d_out;

    k_collect<<<dim3((NANCH + 15) / 16, 2), 256>>>(in);
    k_nms_final<<<2, 1024>>>(in, out);
}

// round 17
// speedup vs baseline: 2.2449x; 1.0118x over previous
#include <cuda_runtime.h>

#define NANCH 8732
#define NCLS  599
#define MC    300
#define CAPN  1024
#define ROWD  604
#define TH_COLLECT 0.9999f

typedef unsigned int u32;
typedef unsigned long long u64;

// ------------------- static device scratch (no allocations) -------------------
__device__ u64 g_col[2 * CAPN];        // collected candidate sortkeys
__device__ u32 g_ccnt[2];              // per-image collected counters (self-resetting)

// -------- speculative collect: all scores >= TH_COLLECT, 2 anchors/warp -------
__device__ __forceinline__ void col_append(int b, u32 c, float f, u32 a) {
    u32 p = atomicAdd(&g_ccnt[b], 1u);
    if (p < CAPN)
        g_col[b * CAPN + p] =
            ((u64)c << 46) | ((u64)__float_as_uint(f) << 14) | (u64)(0x3FFFu - a);
}

__global__ void __launch_bounds__(256) k_collect(const float* __restrict__ in) {
    int b    = blockIdx.y;
    int w    = threadIdx.x >> 5, lane = threadIdx.x & 31;
    int a0   = blockIdx.x * 16 + w * 2;
    bool ok0 = a0 < NANCH, ok1 = a0 + 1 < NANCH;

    const float4* r0 = (const float4*)(in + ((size_t)b * NANCH + a0) * ROWD);
    const float4* r1 = (const float4*)(in + ((size_t)b * NANCH + a0 + 1) * ROWD);

    float4 v[5], u[5];
    #pragma unroll
    for (int i = 0; i < 5; i++) {
        int idx = lane + 32 * i;                 // 0..150 valid (151 float4/row)
        bool inr = idx < 151;
        v[i] = (ok0 && inr) ? __ldg(&r0[idx]) : make_float4(0.f, 0.f, 0.f, 0.f);
        u[i] = (ok1 && inr) ? __ldg(&r1[idx]) : make_float4(0.f, 0.f, 0.f, 0.f);
    }

    #pragma unroll
    for (int i = 0; i < 5; i++) {
        int base = 4 * (lane + 32 * i);
        float fv[4] = {v[i].x, v[i].y, v[i].z, v[i].w};
        float fu[4] = {u[i].x, u[i].y, u[i].z, u[i].w};
        #pragma unroll
        for (int s = 0; s < 4; s++) {
            int j = base + s;                    // raw column; class = j-1
            if (j >= 1 && j <= NCLS) {
                if (fv[s] >= TH_COLLECT) col_append(b, (u32)(j - 1), fv[s], (u32)a0);
                if (fu[s] >= TH_COLLECT) col_append(b, (u32)(j - 1), fu[s], (u32)(a0 + 1));
            }
        }
    }
}

// ---- hybrid bitonic W desc (W in {256,512,1024}, block-uniform; all sync) ----
__device__ __forceinline__ void sortW_desc(u64 p, u64* sm, int tid, int W) {
    if (tid < W) {
        #pragma unroll
        for (int k = 2; k <= 32; k <<= 1)
            #pragma unroll
            for (int j = k >> 1; j; j >>= 1) {
                u64 q = __shfl_xor_sync(0xffffffffu, p, j);
                bool keep_max = ((tid & k) == 0) == ((tid & j) == 0);
                bool sw = keep_max ? (q > p) : (q < p);
                if (sw) p = q;
            }
        sm[tid] = p;
    }
    __syncthreads();
    for (int k = 64; k <= W; k <<= 1) {
        for (int j = k >> 1; j >= 32; j >>= 1) {
            if (tid < W) {
                int x = tid ^ j;
                if (x > tid) {
                    u64 a = sm[tid], bb = sm[x];
                    bool sw = ((tid & k) == 0) ? (a < bb) : (a > bb);
                    if (sw) { sm[tid] = bb; sm[x] = a; }
                }
            }
            __syncthreads();
        }
        if (tid < W) {
            p = sm[tid];
            #pragma unroll
            for (int j = 16; j; j >>= 1) {
                u64 q = __shfl_xor_sync(0xffffffffu, p, j);
                bool keep_max = ((tid & k) == 0) == ((tid & j) == 0);
                bool sw = keep_max ? (q > p) : (q < p);
                if (sw) p = q;
            }
            sm[tid] = p;
        }
        __syncthreads();
    }
}

// --------------------------- shared final-stage pieces ------------------------
struct Cand { bool valid; u32 c, ub, anch; int r; };

// fallback-only: derive rank by backward scan after a full sort
__device__ __forceinline__ Cand extract_rank(const float* __restrict__ in, int b, int tid,
        u32 n, u64* skey, u32* sclass, float4* sbox, float* sarea, u32* skept) {
    Cand cd; cd.valid = (u32)tid < n; cd.c = 0; cd.ub = 0; cd.anch = 0; cd.r = 0;
    skept[tid] = 0;
    if (cd.valid) {
        u64 key = skey[tid];
        cd.c    = (u32)(key >> 46);
        cd.ub   = (u32)(key >> 14);
        cd.anch = 0x3FFFu - (u32)(key & 0x3FFFu);
        sclass[tid] = cd.c;
        const float4 bx = *(const float4*)(in + ((size_t)b * NANCH + cd.anch) * ROWD + 600);
        float y0 = __fsub_rn(bx.y, __fmul_rn(bx.w, 0.5f));
        float x0 = __fsub_rn(bx.x, __fmul_rn(bx.z, 0.5f));
        float y1 = __fadd_rn(bx.y, __fmul_rn(bx.w, 0.5f));
        float x1 = __fadd_rn(bx.x, __fmul_rn(bx.z, 0.5f));
        sbox[tid]  = make_float4(y0, x0, y1, x1);
        sarea[tid] = __fmul_rn(__fsub_rn(y1, y0), __fsub_rn(x1, x0));
        int r = 0;
        while (tid - r - 1 >= 0 && (u32)(skey[tid - r - 1] >> 46) == cd.c) r++;
        cd.r = r;
    }
    __syncthreads();
    return cd;
}

__device__ __forceinline__ bool iou_gt45(float4 bj, float aj, float4 bk, float ak) {
    float ih = fmaxf(__fsub_rn(fminf(bj.z, bk.z), fmaxf(bj.x, bk.x)), 0.f);
    float iw = fmaxf(__fsub_rn(fminf(bj.w, bk.w), fmaxf(bj.y, bk.y)), 0.f);
    float inter = __fmul_rn(ih, iw);
    float uni   = __fsub_rn(__fadd_rn(aj, ak), inter);
    return uni > 0.f && __fdiv_rn(inter, uni) > 0.45f;
}

// serial leader greedy per class segment (segments are tiny; measured-best)
__device__ __forceinline__ void nms_mark(int tid, u32 n, const Cand& cd,
        u32* sclass, float4* sbox, float* sarea, u32* skept) {
    if (cd.valid && cd.r == 0) {                 // one leader per class segment
        skept[tid] = 1;
        for (int k = tid + 1; k < (int)n && sclass[k] == cd.c; k++) {
            float4 bk = sbox[k];
            float  ak = sarea[k];
            bool sup = false;
            for (int j = tid; j < k; j++) {
                if (skept[j] && iou_gt45(sbox[j], sarea[j], bk, ak)) { sup = true; break; }
            }
            skept[k] = sup ? 0u : 1u;
        }
    }
    __syncthreads();
}

// final key packs everything: (score, ~flat, anchor); flat<2^18, anchor<2^14
__device__ __forceinline__ u64 pack_fk(const Cand& cd, const u32* skept, int tid) {
    if (cd.valid && skept[tid] && cd.r < MC) {
        u32 flat = cd.c * MC + (u32)cd.r;
        return ((u64)cd.ub << 32) | ((u64)(0x3FFFFu ^ flat) << 14) | (u64)cd.anch;
    }
    return 0ull;
}

// emit top-200 (skey sorted desc) with exact inverse transform
__device__ __forceinline__ void emit200(const float* __restrict__ in,
        float* __restrict__ out, int b, int tid, const u64* skey) {
    if (tid < 200) {
        u64 key = skey[tid];
        float cls = 0.f, score = 0.f, ocx = 0.f, ocy = 0.f, otw = 0.f, oth = 0.f;
        if (key) {
            score = __uint_as_float((u32)(key >> 32));
            u32 flat = 0x3FFFFu ^ ((u32)(key >> 14) & 0x3FFFFu);
            cls = (float)(flat / MC + 1);
            u32 anchor = (u32)key & 0x3FFFu;
            const float4 bx = *(const float4*)(in + ((size_t)b * NANCH + anchor) * ROWD + 600);
            float y0 = __fsub_rn(bx.y, __fmul_rn(bx.w, 0.5f));
            float x0 = __fsub_rn(bx.x, __fmul_rn(bx.z, 0.5f));
            float y1 = __fadd_rn(bx.y, __fmul_rn(bx.w, 0.5f));
            float x1 = __fadd_rn(bx.x, __fmul_rn(bx.z, 0.5f));
            otw = __fsub_rn(x1, x0);
            oth = __fsub_rn(y1, y0);
            ocx = __fadd_rn(x0, __fmul_rn(otw, 0.5f));
            ocy = __fadd_rn(y0, __fmul_rn(oth, 0.5f));
        }
        float* o = out + ((size_t)b * 200 + tid) * 6;
        o[0] = cls; o[1] = score; o[2] = ocx; o[3] = ocy; o[4] = otw; o[5] = oth;
    }
}

// ---- final: counting-sort + pruned final sort; inline exact fallback ----
__global__ void __launch_bounds__(1024, 1) k_nms_final(const float* __restrict__ in,
                                                       float* __restrict__ out) {
    __shared__ u64    skey[1024];
    __shared__ u32    sclass[1024];
    __shared__ float4 sbox[1024];
    __shared__ float  sarea[1024];
    __shared__ u32    skept[1024];
    __shared__ u32    hist[NCLS + 1];
    __shared__ u32    sbase[NCLS + 1];
    __shared__ u32    wsum[32];
    __shared__ u32    scnt, s_cut, s_sel, s_K;

    int b = blockIdx.x, tid = threadIdx.x;
    int lane = tid & 31, wid = tid >> 5;
    u32 raw = g_ccnt[b];
    u32 n = min(raw, (u32)CAPN);

    // ======== phase A: counting sort by class (O(n)) ========
    u64 myk = ((u32)tid < n) ? g_col[b * CAPN + tid] : 0ull;
    u32 myc = (u32)(myk >> 46);
    if (tid <= NCLS) hist[tid] = 0;
    skey[tid] = 0;
    __syncthreads();
    if ((u32)tid < n) atomicAdd(&hist[myc], 1u);
    __syncthreads();

    // exclusive scan over 600 bins: warp shfl scan + warp-total scan
    u32 cnt0 = (tid <= NCLS) ? hist[tid] : 0;
    u32 inc = cnt0;
    #pragma unroll
    for (int off = 1; off < 32; off <<= 1) {
        u32 o = __shfl_up_sync(0xffffffffu, inc, off);
        if (lane >= off) inc += o;
    }
    if (wid < 20 && lane == 31) wsum[wid] = inc;
    __syncthreads();
    if (tid < 32) {
        u32 wv = (tid < 20) ? wsum[tid] : 0;
        #pragma unroll
        for (int off = 1; off < 32; off <<= 1) {
            u32 o = __shfl_up_sync(0xffffffffu, wv, off);
            if (lane >= off) wv += o;
        }
        wsum[tid] = wv;                          // inclusive warp totals
    }
    __syncthreads();
    if (tid <= NCLS) {
        u32 woffs = (wid > 0) ? wsum[wid - 1] : 0;
        sbase[tid] = woffs + inc - cnt0;         // exclusive prefix
        hist[tid] = 0;                           // reuse as scatter cursor
    }
    __syncthreads();

    if ((u32)tid < n) {
        u32 pos = sbase[myc] + atomicAdd(&hist[myc], 1u);
        skey[pos] = myk;
    }
    __syncthreads();

    // per-segment insertion sort desc by leader (segments are tiny; keys unique)
    {
        u64 kk = skey[tid];
        u32 c2 = (u32)(kk >> 46);
        if ((u32)tid < n && tid == (int)sbase[c2]) {
            int len = (int)hist[c2];
            for (int i = 1; i < len; i++) {
                u64 v = skey[tid + i];
                int j = i - 1;
                while (j >= 0 && skey[tid + j] < v) { skey[tid + j + 1] = skey[tid + j]; j--; }
                skey[tid + j + 1] = v;
            }
        }
    }
    __syncthreads();

    // extract fields, rank = tid - segment base, load boxes
    Cand cd; cd.valid = (u32)tid < n; cd.c = 0; cd.ub = 0; cd.anch = 0; cd.r = 0;
    skept[tid] = 0;
    if (cd.valid) {
        u64 key = skey[tid];
        cd.c    = (u32)(key >> 46);
        cd.ub   = (u32)(key >> 14);
        cd.anch = 0x3FFFu - (u32)(key & 0x3FFFu);
        cd.r    = tid - (int)sbase[cd.c];
        sclass[tid] = cd.c;
        const float4 bx = *(const float4*)(in + ((size_t)b * NANCH + cd.anch) * ROWD + 600);
        float y0 = __fsub_rn(bx.y, __fmul_rn(bx.w, 0.5f));
        float x0 = __fsub_rn(bx.x, __fmul_rn(bx.z, 0.5f));
        float y1 = __fadd_rn(bx.y, __fmul_rn(bx.w, 0.5f));
        float x1 = __fadd_rn(bx.x, __fmul_rn(bx.z, 0.5f));
        sbox[tid]  = make_float4(y0, x0, y1, x1);
        sarea[tid] = __fmul_rn(__fsub_rn(y1, y0), __fsub_rn(x1, x0));
    }
    __syncthreads();

    // fastok: >=200 distinct classes collected => kept-set superset of true top-200
    int D = __syncthreads_count(cd.valid && cd.r == 0);
    bool fastok = (D >= 200) && (raw <= (u32)CAPN);   // block-uniform

    if (fastok) {
        nms_mark(tid, n, cd, sclass, sbox, sarea, skept);
        u64 fk = pack_fk(cd, skept, tid);

        // ---- score-histogram prune: find cutbin s.t. suffix count >= 200 ----
        const u32 BMIN = 0x3F7FE000u;            // below all fast-path score bits
        int bin = -1;
        if (fk) {
            u32 sb2 = (u32)(fk >> 32);
            u32 d2 = (sb2 >= BMIN) ? ((sb2 - BMIN) >> 4) : 0u;
            bin = (int)min(d2, 511u);
        }
        if (tid < 512) hist[tid] = 0;
        if (tid == 0) { s_cut = 0; s_sel = 0; s_K = 0; scnt = 0; }
        __syncthreads();
        if (fk) atomicAdd(&hist[bin], 1u);
        __syncthreads();
        u32 cnt2 = (tid < 512) ? hist[tid] : 0;
        u32 inc2 = cnt2;
        #pragma unroll
        for (int off = 1; off < 32; off <<= 1) {
            u32 o = __shfl_up_sync(0xffffffffu, inc2, off);
            if (lane >= off) inc2 += o;
        }
        if (wid < 16 && lane == 31) wsum[wid] = inc2;
        __syncthreads();
        if (tid < 32) {
            u32 wv = (tid < 16) ? wsum[tid] : 0;
            #pragma unroll
            for (int off = 1; off < 32; off <<= 1) {
                u32 o = __shfl_up_sync(0xffffffffu, wv, off);
                if (lane >= off) wv += o;
            }
            wsum[tid] = wv;
        }
        __syncthreads();
        u32 incl = 0;
        if (tid < 512) {
            incl = ((wid > 0) ? wsum[wid - 1] : 0) + inc2;   // inclusive prefix
            if (tid == 511) s_K = incl;
        }
        __syncthreads();
        if (tid < 512) {
            u32 K = s_K;
            u32 suff = K - (incl - cnt2);        // count of keys with bin >= tid
            if (suff >= 200 && suff - cnt2 < 200) { s_cut = (u32)tid; s_sel = suff; }
        }
        if (tid == 0 && s_K < 200) { s_cut = 0; s_sel = s_K; }
        __syncthreads();

        // ---- compact selected keys (order-free; sort restores exact order) ----
        u64* cbuf = (u64*)sbox;                  // sbox dead after pack_fk
        if (fk && bin >= (int)s_cut) cbuf[atomicAdd(&scnt, 1u)] = fk;
        __syncthreads();
        u32 sel = scnt;
        int W = (sel <= 256) ? 256 : (sel <= 512) ? 512 : 1024;
        u64 p2 = ((u32)tid < sel) ? cbuf[tid] : 0ull;
        sortW_desc(p2, skey, tid, W);
        emit200(in, out, b, tid, skey);
    } else {
        // ======== exact fallback (correctness anchor; never taken in practice) ====
        float m = 0.f;
        if (tid < NCLS) {
            #pragma unroll 1
            for (int a = 0; a < NANCH; a++)
                m = fmaxf(m, __ldg(&in[((size_t)b * NANCH + a) * ROWD + 1 + tid]));
        }
        u64 pm = (tid < NCLS && m > 0.01f)
               ? (((u64)__float_as_uint(m) << 32) | (u32)(~(u32)(tid * MC))) : 0ull;
        sortW_desc(pm, skey, tid, 1024);
        u32 th = (u32)(skey[199] >> 32);             // exact tkey-hi for collection
        __syncthreads();

        if (tid == 0) scnt = 0;
        __syncthreads();
        if (tid < NCLS) {
            #pragma unroll 1
            for (int a = 0; a < NANCH; a++) {
                float v = __ldg(&in[((size_t)b * NANCH + a) * ROWD + 1 + tid]);
                if (v > 0.01f && __float_as_uint(v) >= th) {
                    u32 pos = atomicAdd(&scnt, 1u);
                    if (pos < CAPN)
                        skey[pos] = ((u64)tid << 46) | ((u64)__float_as_uint(v) << 14)
                                  | (u64)(0x3FFFu - (u32)a);
                }
            }
        }
        __syncthreads();
        n = min(scnt, (u32)CAPN);
        u64 q = ((u32)tid < n) ? skey[tid] : 0ull;
        __syncthreads();
        sortW_desc(q, skey, tid, 1024);
        cd = extract_rank(in, b, tid, n, skey, sclass, sbox, sarea, skept);
        nms_mark(tid, n, cd, sclass, sbox, sarea, skept);
        u64 fk = pack_fk(cd, skept, tid);
        __syncthreads();                             // skey readers done
        sortW_desc(fk, skey, tid, 1024);
        emit200(in, out, b, tid, skey);
    }

    // self-reset for the next graph replay (all g_col/g_ccnt reads are done)
    if (tid == 0) g_ccnt[b] = 0;
}

// ------------------------------------------------------------------------------
extern "C" void kernel_launch(void* const* d_in, const int* in_sizes, int n_in,
                              void* d_out, int out_size) {
    const float* in = (const float*)d_in[0];
    float* out = (float*)d_out;

    k_collect<<<dim3((NANCH + 15) / 16, 2), 256>>>(in);
    k_nms_final<<<2, 1024>>>(in, out);
}